// round 3
// baseline (speedup 1.0000x reference)
#include <cuda_runtime.h>
#include <stdint.h>

// Key space: b in [0,256), px,py,pz in [0,128)  ->  2^29 keys -> 2^24 32-bit words
#define NWORDS   (1u << 24)
#define TPB      256
#define WPT      16                      // words per thread in scan kernels
#define BLK_WORDS (TPB * WPT)            // 4096 words per block
#define NBLK     (NWORDS / BLK_WORDS)    // 4096 blocks

__device__ uint32_t           g_bitmap[NWORDS];    // 64 MB presence bitmap
__device__ unsigned long long g_rankWord[NWORDS];  // 128 MB: (word<<32) | exclusive-rank
__device__ uint32_t           g_blockSums[NBLK];
__device__ uint32_t           g_blockOffsets[NBLK];

// ---------------------------------------------------------------- K0: init
// Zero bitmap; prefill output: coords rows = -1, feats = 0.
__global__ __launch_bounds__(TPB) void k0_init(float* __restrict__ out, uint32_t n)
{
    uint32_t i = blockIdx.x * TPB + threadIdx.x;
    if (i < NWORDS / 4)
        ((uint4*)g_bitmap)[i] = make_uint4(0u, 0u, 0u, 0u);
    uint32_t tot4 = (5u * n) / 4;        // coords: n float4 rows, feats: n/4 float4
    if (i < tot4) {
        float4 v = (i < n) ? make_float4(-1.f, -1.f, -1.f, -1.f)
                           : make_float4(0.f, 0.f, 0.f, 0.f);
        ((float4*)out)[i] = v;
    }
}

__device__ __forceinline__ uint32_t make_key(int4 c)
{
    return ((uint32_t)c.x << 21) | ((uint32_t)(c.y >> 1) << 14)
         | ((uint32_t)(c.z >> 1) << 7) | (uint32_t)(c.w >> 1);
}

// ---------------------------------------------------------------- K1: mark
__global__ __launch_bounds__(TPB) void k1_build(const int4* __restrict__ coords, int n)
{
    int i = blockIdx.x * TPB + threadIdx.x;
    if (i >= n) return;
    uint32_t key = make_key(coords[i]);
    atomicOr(&g_bitmap[key >> 5], 1u << (key & 31));
}

// ---------------------------------------------------------------- K2: block popcounts
__global__ __launch_bounds__(TPB) void k2_count()
{
    __shared__ uint32_t s[TPB];
    uint32_t t = threadIdx.x;
    uint32_t base = blockIdx.x * BLK_WORDS + t * WPT;
    const uint4* p = (const uint4*)(g_bitmap + base);
    uint32_t tot = 0;
#pragma unroll
    for (int i = 0; i < 4; i++) {
        uint4 v = p[i];
        tot += __popc(v.x) + __popc(v.y) + __popc(v.z) + __popc(v.w);
    }
    s[t] = tot; __syncthreads();
#pragma unroll
    for (int o = TPB / 2; o > 0; o >>= 1) {
        if (t < o) s[t] += s[t + o];
        __syncthreads();
    }
    if (t == 0) g_blockSums[blockIdx.x] = s[0];
}

// ---------------------------------------------------------------- K3: scan 4096 block sums
__global__ __launch_bounds__(1024) void k3_scan()
{
    __shared__ uint32_t s[1024];
    uint32_t t = threadIdx.x;
    uint32_t v[4], tot = 0;
#pragma unroll
    for (int i = 0; i < 4; i++) { v[i] = g_blockSums[t * 4 + i]; tot += v[i]; }
    s[t] = tot; __syncthreads();
    for (int o = 1; o < 1024; o <<= 1) {
        uint32_t x = (t >= o) ? s[t - o] : 0u;
        __syncthreads();
        s[t] += x;
        __syncthreads();
    }
    uint32_t ex = s[t] - tot;
#pragma unroll
    for (int i = 0; i < 4; i++) { g_blockOffsets[t * 4 + i] = ex; ex += v[i]; }
}

// ---------------------------------------------------------------- K4: emit coords + (word|rank)
__global__ __launch_bounds__(TPB) void k4_emit(float* __restrict__ out)
{
    __shared__ uint32_t s[TPB];
    uint32_t t = threadIdx.x;
    uint32_t base = blockIdx.x * BLK_WORDS + t * WPT;
    uint32_t words[WPT];
    const uint4* p = (const uint4*)(g_bitmap + base);
    uint32_t tot = 0;
#pragma unroll
    for (int i = 0; i < 4; i++) {
        uint4 v = p[i];
        words[4 * i + 0] = v.x; words[4 * i + 1] = v.y;
        words[4 * i + 2] = v.z; words[4 * i + 3] = v.w;
    }
#pragma unroll
    for (int i = 0; i < WPT; i++) tot += __popc(words[i]);
    s[t] = tot; __syncthreads();
    for (int o = 1; o < TPB; o <<= 1) {
        uint32_t x = (t >= o) ? s[t - o] : 0u;
        __syncthreads();
        s[t] += x;
        __syncthreads();
    }
    uint32_t running = g_blockOffsets[blockIdx.x] + (s[t] - tot);
    float4* outc = (float4*)out;
#pragma unroll
    for (int i = 0; i < WPT; i++) {
        uint32_t w = base + i;
        uint32_t word = words[i];
        g_rankWord[w] = ((unsigned long long)word << 32) | (unsigned long long)running;
        while (word) {
            int b = __ffs(word) - 1;
            word &= word - 1;
            uint32_t key = (w << 5) + (uint32_t)b;
            outc[running++] = make_float4((float)(key >> 21),
                                          (float)((key >> 14) & 127),
                                          (float)((key >> 7) & 127),
                                          (float)(key & 127));
        }
    }
}

// ---------------------------------------------------------------- K5: scatter feats
__global__ __launch_bounds__(TPB) void k5_feats(const int4* __restrict__ coords,
                                                const float* __restrict__ kern,
                                                float* __restrict__ outF, int n)
{
    int i = blockIdx.x * TPB + threadIdx.x;
    if (i >= n) return;
    int4 c = coords[i];
    int pos = (c.y & 1) | ((c.z & 1) << 1) | ((c.w & 1) << 2);
    uint32_t key = make_key(c);
    uint32_t w = key >> 5, bit = key & 31;
    unsigned long long rw = g_rankWord[w];
    uint32_t word = (uint32_t)(rw >> 32);
    uint32_t rank = (uint32_t)rw + __popc(word & ((1u << bit) - 1u));
    float contrib = (float)(1 << pos) * __ldg(&kern[pos]);
    atomicAdd(&outF[rank], contrib);
}

// ---------------------------------------------------------------- launch
extern "C" void kernel_launch(void* const* d_in, const int* in_sizes, int n_in,
                              void* d_out, int out_size)
{
    const int4*  coords = (const int4*)d_in[0];
    const float* kern   = (const float*)d_in[1];
    float*       out    = (float*)d_out;
    int n = in_sizes[0] / 4;                 // number of points (rows)

    uint32_t initThreads = (5u * (uint32_t)n) / 4;
    if (initThreads < NWORDS / 4) initThreads = NWORDS / 4;
    k0_init<<<(initThreads + TPB - 1) / TPB, TPB>>>(out, (uint32_t)n);
    k1_build<<<(n + TPB - 1) / TPB, TPB>>>(coords, n);
    k2_count<<<NBLK, TPB>>>();
    k3_scan<<<1, 1024>>>();
    k4_emit<<<NBLK, TPB>>>(out);
    k5_feats<<<(n + TPB - 1) / TPB, TPB>>>(coords, kern, out + 4ll * n, n);
}

// round 4
// speedup vs baseline: 2.4575x; 2.4575x over previous
#include <cuda_runtime.h>
#include <stdint.h>

// Key space: b in [0,256), px,py,pz in [0,128)  ->  2^29 keys -> 2^24 32-bit words
#define NWORDS    (1u << 24)
#define TPB       256
#define WPT       16                      // words per thread in the sweep
#define BLK_WORDS (TPB * WPT)             // 4096 words per block
#define NBLK      (NWORDS / BLK_WORDS)    // 4096 blocks
#define NSEG      (NWORDS / 8)            // 8-word (32B sector) segments

#define FLAG_AGG  (1u << 30)
#define FLAG_PRE  (2u << 30)
#define VAL_MASK  0x3FFFFFFFu

__device__ uint32_t g_bitmap[NWORDS];     // 64 MB presence bitmap
__device__ uint32_t g_segBase[NSEG];      //  8 MB absolute rank at each 8-word segment
__device__ uint32_t g_status[NBLK];       // decoupled-lookback status (flag|value)

// ---------------------------------------------------------------- K0: init
// Zero bitmap, feats region of out, and lookback status.
__global__ __launch_bounds__(TPB) void k0_init(float* __restrict__ outF, uint32_t n)
{
    uint32_t i = blockIdx.x * TPB + threadIdx.x;
    uint32_t bm4 = NWORDS / 4;                    // 4M uint4 for bitmap
    uint32_t ft4 = n / 4;                         // 1M uint4 for feats
    if (i < bm4) {
        ((uint4*)g_bitmap)[i] = make_uint4(0u, 0u, 0u, 0u);
    } else if (i < bm4 + ft4) {
        ((float4*)outF)[i - bm4] = make_float4(0.f, 0.f, 0.f, 0.f);
    } else if (i < bm4 + ft4 + NBLK) {
        g_status[i - (bm4 + ft4)] = 0u;
    }
}

__device__ __forceinline__ uint32_t make_key(int4 c)
{
    return ((uint32_t)c.x << 21) | ((uint32_t)(c.y >> 1) << 14)
         | ((uint32_t)(c.z >> 1) << 7) | (uint32_t)(c.w >> 1);
}

// ---------------------------------------------------------------- K1: mark bits
__global__ __launch_bounds__(TPB) void k1_build(const int4* __restrict__ coords, int n)
{
    int i = blockIdx.x * TPB + threadIdx.x;
    if (i >= n) return;
    uint32_t key = make_key(coords[i]);
    atomicOr(&g_bitmap[key >> 5], 1u << (key & 31));
}

// ---------------------------------------------------------------- K2: fused sweep
// Single pass over the bitmap: block popcount + scan, decoupled lookback for
// the global exclusive prefix, then emit sorted out_coords + segment rank bases.
__global__ __launch_bounds__(TPB) void k2_sweep(float* __restrict__ out)
{
    __shared__ uint32_t s[TPB];
    __shared__ uint32_t s_excl;
    uint32_t t   = threadIdx.x;
    uint32_t bid = blockIdx.x;
    uint32_t base = bid * BLK_WORDS + t * WPT;

    uint32_t words[WPT];
    const uint4* p = (const uint4*)(g_bitmap + base);
    uint32_t tot = 0;
#pragma unroll
    for (int i = 0; i < 4; i++) {
        uint4 v = p[i];
        words[4 * i + 0] = v.x; words[4 * i + 1] = v.y;
        words[4 * i + 2] = v.z; words[4 * i + 3] = v.w;
    }
#pragma unroll
    for (int i = 0; i < WPT; i++) tot += __popc(words[i]);

    // block-wide inclusive scan of per-thread popcounts
    s[t] = tot; __syncthreads();
    for (int o = 1; o < TPB; o <<= 1) {
        uint32_t x = (t >= o) ? s[t - o] : 0u;
        __syncthreads();
        s[t] += x;
        __syncthreads();
    }
    uint32_t blockAgg = s[TPB - 1];

    // publish aggregate ASAP (block 0 publishes its final prefix directly)
    if (t == 0) {
        if (bid == 0) {
            atomicExch(&g_status[0], FLAG_PRE | blockAgg);
            s_excl = 0u;
        } else {
            atomicExch(&g_status[bid], FLAG_AGG | blockAgg);
        }
    }

    // warp 0: decoupled lookback
    if (bid != 0 && t < 32) {
        uint32_t excl = 0;
        int pos = (int)bid - 1;
        while (pos >= 0) {
            int idx = pos - (int)t;
            uint32_t sv;
            if (idx >= 0) {
                do { sv = *((volatile uint32_t*)&g_status[idx]); }
                while ((sv >> 30) == 0u);
            } else {
                sv = FLAG_PRE;  // virtual prefix of 0
            }
            uint32_t flag = sv >> 30;
            uint32_t val  = sv & VAL_MASK;
            uint32_t ball = __ballot_sync(0xFFFFFFFFu, flag == 2u);
            if (ball) {
                int fp = __ffs(ball) - 1;           // nearest PREFIX lane
                uint32_t contrib = ((int)t <= fp) ? val : 0u;
                excl += __reduce_add_sync(0xFFFFFFFFu, contrib);
                break;
            } else {                                 // 32 aggregates
                excl += __reduce_add_sync(0xFFFFFFFFu, val);
                pos -= 32;
            }
        }
        if (t == 0) {
            atomicExch(&g_status[bid], FLAG_PRE | ((excl + blockAgg) & VAL_MASK));
            s_excl = excl;
        }
    }
    __syncthreads();

    // emit: coords for each set bit (sorted order) + per-segment rank bases
    uint32_t running = s_excl + (s[t] - tot);
    float4* outc = (float4*)out;
#pragma unroll
    for (int i = 0; i < WPT; i++) {
        uint32_t w = base + i;
        if ((i & 7) == 0) g_segBase[w >> 3] = running;
        uint32_t word = words[i];
        while (word) {
            int b = __ffs(word) - 1;
            word &= word - 1;
            uint32_t key = (w << 5) + (uint32_t)b;
            outc[running++] = make_float4((float)(key >> 21),
                                          (float)((key >> 14) & 127),
                                          (float)((key >> 7) & 127),
                                          (float)(key & 127));
        }
    }
}

// ---------------------------------------------------------------- K3: tail fill
// Fill out_coords rows [total, n) with -1 (jnp.unique padding).
__global__ __launch_bounds__(TPB) void k3_tail(float* __restrict__ out, int n)
{
    uint32_t total = g_status[NBLK - 1] & VAL_MASK;
    float4* outc = (float4*)out;
    for (uint32_t i = total + blockIdx.x * blockDim.x + threadIdx.x;
         i < (uint32_t)n; i += gridDim.x * blockDim.x)
        outc[i] = make_float4(-1.f, -1.f, -1.f, -1.f);
}

// ---------------------------------------------------------------- K4: scatter feats
__global__ __launch_bounds__(TPB) void k4_feats(const int4* __restrict__ coords,
                                                const float* __restrict__ kern,
                                                float* __restrict__ outF, int n)
{
    int i = blockIdx.x * TPB + threadIdx.x;
    if (i >= n) return;
    int4 c = coords[i];
    int pos = (c.y & 1) | ((c.z & 1) << 1) | ((c.w & 1) << 2);
    uint32_t key = make_key(c);
    uint32_t w = key >> 5, bit = key & 31;
    uint32_t seg = w >> 3, j = w & 7;

    // one 32B sector: the 8 bitmap words of this segment
    const uint4* sp = (const uint4*)(g_bitmap + (seg << 3));
    uint4 lo = sp[0], hi = sp[1];
    uint32_t sw[8] = { lo.x, lo.y, lo.z, lo.w, hi.x, hi.y, hi.z, hi.w };

    uint32_t rank = g_segBase[seg];
#pragma unroll
    for (uint32_t k = 0; k < 8; k++)
        if (k < j) rank += __popc(sw[k]);
    rank += __popc(sw[j] & ((1u << bit) - 1u));

    float contrib = (float)(1 << pos) * __ldg(&kern[pos]);
    atomicAdd(&outF[rank], contrib);
}

// ---------------------------------------------------------------- launch
extern "C" void kernel_launch(void* const* d_in, const int* in_sizes, int n_in,
                              void* d_out, int out_size)
{
    const int4*  coords = (const int4*)d_in[0];
    const float* kern   = (const float*)d_in[1];
    float*       out    = (float*)d_out;
    int n = in_sizes[0] / 4;                     // number of points

    float* outF = out + 4ll * n;                 // feats region

    uint32_t initThreads = NWORDS / 4 + (uint32_t)n / 4 + NBLK;
    k0_init<<<(initThreads + TPB - 1) / TPB, TPB>>>(outF, (uint32_t)n);
    k1_build<<<(n + TPB - 1) / TPB, TPB>>>(coords, n);
    k2_sweep<<<NBLK, TPB>>>(out);
    k3_tail<<<256, TPB>>>(out, n);
    k4_feats<<<(n + TPB - 1) / TPB, TPB>>>(coords, kern, outF, n);
}